// round 14
// baseline (speedup 1.0000x reference)
#include <cuda_runtime.h>

// DeepPoly ReLU relaxation, elementwise over N=16,777,216 floats.
// inputs: lb, ub, alpha (fp32, N each). output: [out_lb (N) | out_ub (N)] fp32.
//
// HBM-roofline-saturated — FINAL KERNEL (search closed).
// 20 B/elem mandatory traffic (3 reads + 2 writes, no reuse) = 336 MB
// @ up to 6.58 TB/s achieved (83.1% of 8 TB/s spec). Residual is DRAM
// read/write turnaround on a 3:2 mix; not software-addressable (LTS cap is
// path-independent, HBM striding not a lever, per B300 microarch).
//
// Block-size parabola, fully resolved (kernel-only us / occ / DRAM%):
//   512 thr: 45.4  / 75.8% / 78.8%   regress
//   256 thr: 43.6-45.3 / ~80% / 78-82%
//   128 thr: 42.88, 43.55 / 84-85% / 81.8-83.1%   <- OPTIMUM (this kernel)
//    64 thr: 45.1  / 81.7% / 79.7%   regress (CTA dispatch overhead @32/SM)
// Other axes settled: cache hints neutral (R3/R4); 2 quads/thread regress
// (R2: regs 40, occ 60%); 256-bit v8 ld/st rejected (same failure mode);
// bounds-check elision neutral (R4).
// Shape: 128 thr/block, 32768 blocks, 1 float4/thread, 29 regs.

__global__ __launch_bounds__(128) void verify_relu_kernel(
    const float4* __restrict__ lb4,
    const float4* __restrict__ ub4,
    const float4* __restrict__ al4,
    float4* __restrict__ olb4,
    float4* __restrict__ oub4,
    int n4)
{
    int i = blockIdx.x * blockDim.x + threadIdx.x;
    if (i >= n4) return;

    float4 lb = lb4[i];
    float4 ub = ub4[i];
    float4 al = al4[i];

    float4 olb, oub;

    #pragma unroll
    for (int k = 0; k < 4; k++) {
        float l = (&lb.x)[k];
        float u = (&ub.x)[k];
        float a = (&al.x)[k];

        float ca    = fminf(fmaxf(a, 0.0f), 1.0f);
        float slope = fmaxf(u / (u - l), 0.0f);

        float uc_diag = (l > 0.0f) ? 1.0f : slope;
        float uc_bias = (l > 0.0f) ? 0.0f : (-(slope * l));
        float lc_diag = (u < 0.0f) ? 0.0f : ca;

        (&olb.x)[k] = l * lc_diag;
        (&oub.x)[k] = fmaf(u, uc_diag, uc_bias);
    }

    olb4[i] = olb;
    oub4[i] = oub;
}

extern "C" void kernel_launch(void* const* d_in, const int* in_sizes, int n_in,
                              void* d_out, int out_size) {
    const float* lb    = (const float*)d_in[0];
    const float* ub    = (const float*)d_in[1];
    const float* alpha = (const float*)d_in[2];
    float* out = (float*)d_out;

    int n  = in_sizes[0];        // 16777216
    int n4 = n / 4;              // 4194304

    float* out_lb = out;
    float* out_ub = out + n;

    int threads = 128;
    int blocks  = (n4 + threads - 1) / threads;   // 32768

    verify_relu_kernel<<<blocks, threads>>>(
        (const float4*)lb, (const float4*)ub, (const float4*)alpha,
        (float4*)out_lb, (float4*)out_ub, n4);
}

// round 15
// speedup vs baseline: 1.0018x; 1.0018x over previous
#include <cuda_runtime.h>

// DeepPoly ReLU relaxation, elementwise over N=16,777,216 floats.
// inputs: lb, ub, alpha (fp32, N each). output: [out_lb (N) | out_ub (N)] fp32.
//
// HBM-roofline-saturated — FINAL KERNEL (search closed; 13 benches).
// 20 B/elem mandatory traffic (3 reads + 2 writes, no reuse) = 336 MB
// @ 6.5-6.6 TB/s achieved (82-83% of 8 TB/s spec). Residual is DRAM
// read/write turnaround on a 3:2 mix; not software-addressable (LTS cap is
// path-independent, HBM striding not a lever, per B300 microarch).
//
// Block-size parabola, resolved (kernel-only us / occ / DRAM%):
//   512 thr: 45.4  / 75.8% / 78.8%   regress
//   256 thr: 43.6-45.3 / ~80% / 78-82%
//   128 thr: 42.88, 43.39, 43.55 / 84-85% / 81.6-83.1%  <- OPTIMUM (3x benched)
//    64 thr: 45.1  / 81.7% / 79.7%   regress (CTA dispatch overhead @32/SM)
// Other axes settled: cache hints neutral; 2 quads/thread regress (occ 60%);
// 256-bit v8 ld/st rejected (reg-pressure failure mode); bounds check free.
// Shape: 128 thr/block, 32768 blocks, 1 float4/thread, 29 regs.

__global__ __launch_bounds__(128) void verify_relu_kernel(
    const float4* __restrict__ lb4,
    const float4* __restrict__ ub4,
    const float4* __restrict__ al4,
    float4* __restrict__ olb4,
    float4* __restrict__ oub4,
    int n4)
{
    int i = blockIdx.x * blockDim.x + threadIdx.x;
    if (i >= n4) return;

    float4 lb = lb4[i];
    float4 ub = ub4[i];
    float4 al = al4[i];

    float4 olb, oub;

    #pragma unroll
    for (int k = 0; k < 4; k++) {
        float l = (&lb.x)[k];
        float u = (&ub.x)[k];
        float a = (&al.x)[k];

        float ca    = fminf(fmaxf(a, 0.0f), 1.0f);
        float slope = fmaxf(u / (u - l), 0.0f);

        float uc_diag = (l > 0.0f) ? 1.0f : slope;
        float uc_bias = (l > 0.0f) ? 0.0f : (-(slope * l));
        float lc_diag = (u < 0.0f) ? 0.0f : ca;

        (&olb.x)[k] = l * lc_diag;
        (&oub.x)[k] = fmaf(u, uc_diag, uc_bias);
    }

    olb4[i] = olb;
    oub4[i] = oub;
}

extern "C" void kernel_launch(void* const* d_in, const int* in_sizes, int n_in,
                              void* d_out, int out_size) {
    const float* lb    = (const float*)d_in[0];
    const float* ub    = (const float*)d_in[1];
    const float* alpha = (const float*)d_in[2];
    float* out = (float*)d_out;

    int n  = in_sizes[0];        // 16777216
    int n4 = n / 4;              // 4194304

    float* out_lb = out;
    float* out_ub = out + n;

    int threads = 128;
    int blocks  = (n4 + threads - 1) / threads;   // 32768

    verify_relu_kernel<<<blocks, threads>>>(
        (const float4*)lb, (const float4*)ub, (const float4*)alpha,
        (float4*)out_lb, (float4*)out_ub, n4);
}

// round 16
// speedup vs baseline: 1.0054x; 1.0036x over previous
#include <cuda_runtime.h>

// DeepPoly ReLU relaxation, elementwise over N=16,777,216 floats.
// inputs: lb, ub, alpha (fp32, N each). output: [out_lb (N) | out_ub (N)] fp32.
//
// HBM-roofline-saturated — TERMINAL KERNEL (search closed; 14 benches).
// 20 B/elem mandatory traffic (3 reads + 2 writes, no reuse) = 336 MB
// @ 6.4-6.6 TB/s achieved (80-83% of 8 TB/s spec). Residual is DRAM
// read/write turnaround on a 3:2 mix; not software-addressable (LTS cap is
// path-independent, HBM striding not a lever, per B300 microarch).
//
// Block-size parabola, resolved (kernel-only us / occ / DRAM%):
//   512 thr: 45.4 / 75.8% / 78.8%           regress
//   256 thr: 43.6-45.3 / ~80% / 78-82%
//   128 thr: 42.88-44.03 / 83-85% / 81-83%  <- OPTIMUM (4x benched)
//    64 thr: 45.1 / 81.7% / 79.7%           regress (dispatch overhead @32/SM)
// Other axes settled: cache hints neutral; 2 quads/thread regress (occ 60%);
// 256-bit v8 ld/st rejected (reg-pressure failure mode); bounds check free.
// Shape: 128 thr/block, 32768 blocks, 1 float4/thread, 29 regs.

__global__ __launch_bounds__(128) void verify_relu_kernel(
    const float4* __restrict__ lb4,
    const float4* __restrict__ ub4,
    const float4* __restrict__ al4,
    float4* __restrict__ olb4,
    float4* __restrict__ oub4,
    int n4)
{
    int i = blockIdx.x * blockDim.x + threadIdx.x;
    if (i >= n4) return;

    float4 lb = lb4[i];
    float4 ub = ub4[i];
    float4 al = al4[i];

    float4 olb, oub;

    #pragma unroll
    for (int k = 0; k < 4; k++) {
        float l = (&lb.x)[k];
        float u = (&ub.x)[k];
        float a = (&al.x)[k];

        float ca    = fminf(fmaxf(a, 0.0f), 1.0f);
        float slope = fmaxf(u / (u - l), 0.0f);

        float uc_diag = (l > 0.0f) ? 1.0f : slope;
        float uc_bias = (l > 0.0f) ? 0.0f : (-(slope * l));
        float lc_diag = (u < 0.0f) ? 0.0f : ca;

        (&olb.x)[k] = l * lc_diag;
        (&oub.x)[k] = fmaf(u, uc_diag, uc_bias);
    }

    olb4[i] = olb;
    oub4[i] = oub;
}

extern "C" void kernel_launch(void* const* d_in, const int* in_sizes, int n_in,
                              void* d_out, int out_size) {
    const float* lb    = (const float*)d_in[0];
    const float* ub    = (const float*)d_in[1];
    const float* alpha = (const float*)d_in[2];
    float* out = (float*)d_out;

    int n  = in_sizes[0];        // 16777216
    int n4 = n / 4;              // 4194304

    float* out_lb = out;
    float* out_ub = out + n;

    int threads = 128;
    int blocks  = (n4 + threads - 1) / threads;   // 32768

    verify_relu_kernel<<<blocks, threads>>>(
        (const float4*)lb, (const float4*)ub, (const float4*)alpha,
        (float4*)out_lb, (float4*)out_ub, n4);
}